// round 1
// baseline (speedup 1.0000x reference)
#include <cuda_runtime.h>
#include <math.h>

#define Bdim 64
#define Tdim 1024
#define Edim 512
#define Hdim 1024
#define Vdim 512

#define KSPLIT 8
#define NSPLIT 16
#define NCTA (KSPLIT * NSPLIT)      // 128 CTAs, all co-resident on 148 SMs
#define KS (Hdim / KSPLIT)          // 128 rows of W per CTA
#define NS (Hdim / NSPLIT)          // 64 cols of W per CTA
#define HPAD (KS + 4)               // padded sH row (bank-conflict-free, 16B aligned)

typedef unsigned long long ull;

// ---------------- scratch (device globals: no allocations allowed) ----------------
__device__ __align__(16) float g_xp[Bdim * Tdim * Hdim];        // 256 MB: xproj (B,T,H)
__device__ __align__(16) float g_hs[Bdim * Tdim * Hdim];        // 256 MB: all hidden states (B,T,H)
__device__ __align__(16) float g_h[2][Bdim * Hdim];             // double-buffered h
__device__ __align__(16) float g_partial[KSPLIT][Bdim * Hdim];  // per-kslice partials
__device__ unsigned int g_barrier;                              // monotonic grid barrier

// ---------------- packed fp32x2 helpers (double-rate FFMA on sm_100a) ----------------
__device__ __forceinline__ ull pack2(float x, float y) {
    ull r;
    asm("mov.b64 %0, {%1, %2};" : "=l"(r) : "r"(__float_as_uint(x)), "r"(__float_as_uint(y)));
    return r;
}
__device__ __forceinline__ void unpack2(ull v, float& x, float& y) {
    unsigned lo, hi;
    asm("mov.b64 {%0, %1}, %2;" : "=r"(lo), "=r"(hi) : "l"(v));
    x = __uint_as_float(lo); y = __uint_as_float(hi);
}
__device__ __forceinline__ ull fma2(ull a, ull b, ull c) {
    ull d;
    asm("fma.rn.f32x2 %0, %1, %2, %3;" : "=l"(d) : "l"(a), "l"(b), "l"(c));
    return d;
}

// ---------------- init: zero h0 and barrier counter (every replay) ----------------
__global__ void init_kernel() {
    int i = blockIdx.x * blockDim.x + threadIdx.x;
    if (i == 0) g_barrier = 0u;
    if (i < Bdim * Hdim) g_h[0][i] = 0.0f;
}

// ---------------- generic bias-GEMM: C[M,N] = A[M,K] @ B[K,N] + bias[N] ----------------
// BM=64, BN=64, BK=32, 256 threads, 4x4 per-thread tile via f32x2,
// double-buffered SMEM with register prefetch.
__global__ void __launch_bounds__(256) gemm_bias_kernel(
    const float* __restrict__ A, const float* __restrict__ Bm,
    const float* __restrict__ bias, float* __restrict__ C,
    int M, int N, int K)
{
    __shared__ float sA[2][64][36];  // [m][k] padded: conflict-free scalar reads
    __shared__ float sB[2][32][64];  // [k][n]

    const int tid = threadIdx.x;
    const int tx = tid & 15;        // n-group: cols 4*tx .. 4*tx+3
    const int ty = tid >> 4;        // m-group: rows 4*ty .. 4*ty+3
    const int m0 = blockIdx.y * 64;
    const int n0 = blockIdx.x * 64;
    const int nk = K >> 5;

    const float4* A4 = (const float4*)A;
    const float4* B4 = (const float4*)Bm;
    const int Kq = K >> 2, Nq = N >> 2, n0q = n0 >> 2;

    // prologue: tile 0
#pragma unroll
    for (int i = 0; i < 2; i++) {
        int idx = tid + i * 256;
        int r = idx >> 3, c = idx & 7;                 // A: 64 rows x 8 float4
        float4 v = A4[(size_t)(m0 + r) * Kq + c];
        *(float4*)&sA[0][r][c * 4] = v;
        int r2 = idx >> 4, c2 = idx & 15;              // B: 32 rows x 16 float4
        float4 w = B4[(size_t)r2 * Nq + n0q + c2];
        *(float4*)&sB[0][r2][c2 * 4] = w;
    }
    __syncthreads();

    ull acc[4][2];
#pragma unroll
    for (int i = 0; i < 4; i++) { acc[i][0] = 0ull; acc[i][1] = 0ull; }

    for (int kt = 0; kt < nk; kt++) {
        const int cb = kt & 1;
        float4 pvA[2], pvB[2];
        const bool more = (kt + 1 < nk);
        if (more) {
            int kk = (kt + 1) << 5;
#pragma unroll
            for (int i = 0; i < 2; i++) {
                int idx = tid + i * 256;
                int r = idx >> 3, c = idx & 7;
                pvA[i] = A4[(size_t)(m0 + r) * Kq + (kk >> 2) + c];
                int r2 = idx >> 4, c2 = idx & 15;
                pvB[i] = B4[(size_t)(kk + r2) * Nq + n0q + c2];
            }
        }
#pragma unroll 8
        for (int k = 0; k < 32; k++) {
            float4 wv = *(float4*)&sB[cb][k][tx * 4];
            ull w01 = pack2(wv.x, wv.y);
            ull w23 = pack2(wv.z, wv.w);
#pragma unroll
            for (int i = 0; i < 4; i++) {
                float a = sA[cb][ty * 4 + i][k];
                ull aa = pack2(a, a);
                acc[i][0] = fma2(aa, w01, acc[i][0]);
                acc[i][1] = fma2(aa, w23, acc[i][1]);
            }
        }
        if (more) {
            int nb = cb ^ 1;
#pragma unroll
            for (int i = 0; i < 2; i++) {
                int idx = tid + i * 256;
                int r = idx >> 3, c = idx & 7;
                *(float4*)&sA[nb][r][c * 4] = pvA[i];
                int r2 = idx >> 4, c2 = idx & 15;
                *(float4*)&sB[nb][r2][c2 * 4] = pvB[i];
            }
        }
        __syncthreads();
    }

    float4 bv = *(const float4*)&bias[n0 + tx * 4];
#pragma unroll
    for (int i = 0; i < 4; i++) {
        float x0, x1, x2, x3;
        unpack2(acc[i][0], x0, x1);
        unpack2(acc[i][1], x2, x3);
        float4 o = make_float4(x0 + bv.x, x1 + bv.y, x2 + bv.z, x3 + bv.w);
        *(float4*)&C[(size_t)(m0 + ty * 4 + i) * N + n0 + tx * 4] = o;
    }
}

// ---------------- grid barrier (monotonic counter, release/acquire) ----------------
__device__ __forceinline__ void gbar(unsigned phase) {
    __syncthreads();
    if (threadIdx.x == 0) {
        __threadfence();                    // release all prior stores (CTA-synced above)
        atomicAdd(&g_barrier, 1u);
        const unsigned target = phase * (unsigned)NCTA;
        unsigned* p = &g_barrier;
        unsigned v;
        do {
            asm volatile("ld.acquire.gpu.u32 %0, [%1];" : "=r"(v) : "l"(p));
        } while (v < target);
    }
    __syncthreads();
}

// ---------------- persistent recurrence: 1024 steps of h = tanh(xp_t + h @ W_hh) ----------------
__global__ void __launch_bounds__(256, 1) rnn_recurrence_kernel(
    const float* __restrict__ W_hh, float* __restrict__ hfinal_out)
{
    extern __shared__ float smem[];
    float* sW = smem;                // [KS][NS] = [128][64]
    float* sH = smem + KS * NS;      // [64][HPAD] : h slice, [b][k]

    const int tid = threadIdx.x;
    const int kidx = blockIdx.x / NSPLIT;
    const int nidx = blockIdx.x % NSPLIT;
    const int k0 = kidx * KS, n0 = nidx * NS;
    const int tx = tid & 15, ty = tid >> 4;

    // load W block once; resident in SMEM for all 1024 steps
    {
        const float4* W4 = (const float4*)W_hh;
#pragma unroll
        for (int i = 0; i < 8; i++) {
            int idx = tid + i * 256;
            int r = idx >> 4, c = idx & 15;          // 128 rows x 16 float4
            float4 v = W4[(size_t)(k0 + r) * (Hdim >> 2) + (n0 >> 2) + c];
            *(float4*)&sW[r * NS + c * 4] = v;
        }
    }

    const int rbase = blockIdx.x * (Bdim * Hdim / NCTA);   // 512 reduce elems per CTA
    unsigned bar_phase = 0;

    for (int t = 0; t < Tdim; t++) {
        const float* cur = g_h[t & 1];
        float* nxt = g_h[(t + 1) & 1];

        // load h slice: sH[b][k] = cur[b*H + k0 + k]
        {
            const float4* c4p = (const float4*)cur;
#pragma unroll
            for (int i = 0; i < 8; i++) {
                int idx = tid + i * 256;
                int b = idx >> 5, c = idx & 31;      // 64 rows x 32 float4
                float4 v = c4p[(size_t)b * (Hdim >> 2) + (k0 >> 2) + c];
                *(float4*)&sH[b * HPAD + c * 4] = v;
            }
        }
        __syncthreads();

        // partial(64x64) = hslice(64x128) @ Wblock(128x64)
        ull acc[4][2];
#pragma unroll
        for (int i = 0; i < 4; i++) { acc[i][0] = 0ull; acc[i][1] = 0ull; }

#pragma unroll 8
        for (int k = 0; k < KS; k++) {
            float4 wv = *(float4*)&sW[k * NS + tx * 4];
            ull w01 = pack2(wv.x, wv.y);
            ull w23 = pack2(wv.z, wv.w);
#pragma unroll
            for (int i = 0; i < 4; i++) {
                float a = sH[(ty * 4 + i) * HPAD + k];
                ull aa = pack2(a, a);
                acc[i][0] = fma2(aa, w01, acc[i][0]);
                acc[i][1] = fma2(aa, w23, acc[i][1]);
            }
        }

        // write partial block
        {
            float* pp = g_partial[kidx];
#pragma unroll
            for (int i = 0; i < 4; i++) {
                float x0, x1, x2, x3;
                unpack2(acc[i][0], x0, x1);
                unpack2(acc[i][1], x2, x3);
                float4 o = make_float4(x0, x1, x2, x3);
                *(float4*)&pp[(size_t)(ty * 4 + i) * Hdim + n0 + tx * 4] = o;
            }
        }
        gbar(++bar_phase);

        // distributed reduce: sum KSPLIT partials + xp, tanh, write h/hs (2 elems/thread)
        {
            const int f = rbase + tid * 2;
            const int b = f >> 10;              // / Hdim
            const int hc = f & (Hdim - 1);
            float s0 = 0.f, s1 = 0.f;
#pragma unroll
            for (int kk = 0; kk < KSPLIT; kk++) {
                float2 p = *(const float2*)&g_partial[kk][f];
                s0 += p.x; s1 += p.y;
            }
            const size_t xidx = (size_t)b * Tdim * Hdim + (size_t)t * Hdim + hc;
            const float2 xp = *(const float2*)&g_xp[xidx];
            float v0 = tanhf(s0 + xp.x);
            float v1 = tanhf(s1 + xp.y);
            *(float2*)&nxt[f] = make_float2(v0, v1);
            *(float2*)&g_hs[xidx] = make_float2(v0, v1);
            if (t == Tdim - 1) {
                *(float2*)&hfinal_out[f] = make_float2(v0, v1);
            }
        }
        gbar(++bar_phase);
    }
}

// ---------------- launch ----------------
extern "C" void kernel_launch(void* const* d_in, const int* in_sizes, int n_in,
                              void* d_out, int out_size)
{
    (void)in_sizes; (void)n_in; (void)out_size;
    const float* X    = (const float*)d_in[0];
    const float* W_xh = (const float*)d_in[1];
    const float* b_h  = (const float*)d_in[2];
    const float* W_hh = (const float*)d_in[3];
    const float* W_hy = (const float*)d_in[4];
    const float* b_y  = (const float*)d_in[5];

    float* Y    = (float*)d_out;                          // (B,T,V)
    float* hfin = Y + (size_t)Bdim * Tdim * Vdim;         // (B,H)

    float *pxp = nullptr, *phs = nullptr;
    cudaGetSymbolAddress((void**)&pxp, g_xp);
    cudaGetSymbolAddress((void**)&phs, g_hs);

    // reset h0 + barrier
    init_kernel<<<(Bdim * Hdim + 255) / 256, 256>>>();

    // GEMM1: xp = X @ W_xh + b_h   (M=B*T, K=E, N=H)
    dim3 g1(Hdim / 64, (Bdim * Tdim) / 64);
    gemm_bias_kernel<<<g1, 256>>>(X, W_xh, b_h, pxp, Bdim * Tdim, Hdim, Edim);

    // recurrence (persistent, grid barrier)
    size_t shbytes = (size_t)(KS * NS + Bdim * HPAD) * sizeof(float);   // 66560 B
    cudaFuncSetAttribute(rnn_recurrence_kernel,
                         cudaFuncAttributeMaxDynamicSharedMemorySize, (int)shbytes);
    rnn_recurrence_kernel<<<NCTA, 256, shbytes>>>(W_hh, hfin);

    // GEMM2: Y = hs @ W_hy + b_y   (M=B*T, K=H, N=V)
    dim3 g2(Vdim / 64, (Bdim * Tdim) / 64);
    gemm_bias_kernel<<<g2, 256>>>(phs, W_hy, b_y, Y, Bdim * Tdim, Vdim, Hdim);
}